// round 2
// baseline (speedup 1.0000x reference)
#include <cuda_runtime.h>
#include <math.h>

#define SQ 2048
#define HD 4096
#define NH 32
#define NKV 8
#define DH 128
#define IDIM 11008
#define EPSR 1e-6f
#define NEGF -3.0e38f

// ---------------- scratch (device globals; no runtime allocation) ----------------
__device__ float g_cat [SQ * 2 * HD];   // [S, 8192] concat(embeds, hidden)
__device__ float g_x   [SQ * HD];       // fc out / residual 1
__device__ float g_h   [SQ * HD];       // rmsnorm out (reused for both norms)
__device__ float g_q   [SQ * NH * DH];
__device__ float g_k   [SQ * NKV * DH];
__device__ float g_v   [SQ * NKV * DH];
__device__ float g_attn[SQ * NH * DH];
__device__ float g_x2  [SQ * HD];       // after o-proj + residual
__device__ float g_gate[SQ * IDIM];
__device__ float g_up  [SQ * IDIM];

// ---------------- concat ----------------
__global__ void concat_kernel(const float* __restrict__ embeds,
                              const float* __restrict__ hidden,
                              float* __restrict__ out) {
    int t = blockIdx.x * blockDim.x + threadIdx.x;       // over S*8192/4
    int e = t * 4;
    if (e >= SQ * 2 * HD) return;
    int s = e >> 13;              // /8192
    int i = e & 8191;
    const float* src = (i < HD) ? (embeds + s * HD + i) : (hidden + s * HD + (i - HD));
    *(float4*)(out + e) = *(const float4*)src;
}

// ---------------- rmsnorm ----------------
__global__ void rmsnorm_kernel(const float* __restrict__ x,
                               const float* __restrict__ w,
                               float* __restrict__ out) {
    int row = blockIdx.x;
    const float* xr = x + (size_t)row * HD;
    float ss = 0.f;
    for (int i = threadIdx.x; i < HD; i += 256) { float v = xr[i]; ss += v * v; }
    __shared__ float red[256];
    red[threadIdx.x] = ss;
    __syncthreads();
    for (int o = 128; o > 0; o >>= 1) {
        if (threadIdx.x < o) red[threadIdx.x] += red[threadIdx.x + o];
        __syncthreads();
    }
    float scale = rsqrtf(red[0] / (float)HD + EPSR);
    for (int i = threadIdx.x; i < HD; i += 256)
        out[(size_t)row * HD + i] = xr[i] * scale * w[i];
}

// ---------------- rope (in-place on q and k) ----------------
__global__ void rope_kernel(float* __restrict__ q, float* __restrict__ k) {
    int b = blockIdx.x;
    int s = b / (NH + NKV);
    int h = b - s * (NH + NKV);
    float* ptr = (h < NH) ? (q + ((size_t)s * NH + h) * DH)
                          : (k + ((size_t)s * NKV + (h - NH)) * DH);
    int d = threadIdx.x;   // 0..127
    __shared__ float row[DH];
    row[d] = ptr[d];
    __syncthreads();
    int j = d & 63;
    double invf = pow(10000.0, -(double)j / 64.0);
    float ang = (float)((double)s * invf);     // mimic fp32 product rounding closely
    float c  = (float)cos((double)ang);
    float sn = (float)sin((double)ang);
    float rot = (d < 64) ? -row[d + 64] : row[d - 64];
    ptr[d] = row[d] * c + rot * sn;
}

// ---------------- silu(gate) * up ----------------
__global__ void silu_mul_kernel(const float* __restrict__ g,
                                const float* __restrict__ u,
                                float* __restrict__ out, int n) {
    int i = blockIdx.x * blockDim.x + threadIdx.x;
    if (i < n) {
        float x = g[i];
        float s = x / (1.f + expf(-x));
        out[i] = s * u[i];
    }
}

// ---------------- generic NT GEMM: C[m,n] = sum_k A[m,k]*B[n,k] (+bias[n]) (+res[m,n]) ------
// A: [M,K] row-major, B: [N,K] row-major. M%128==0, N%128==0, K%16==0.
__global__ void __launch_bounds__(256, 2)
gemm_nt(const float* __restrict__ A, const float* __restrict__ B,
        float* __restrict__ C, const float* __restrict__ bias,
        const float* __restrict__ res, int M, int N, int K) {
    __shared__ float As[16][128];
    __shared__ float Bs[16][128];
    int tid = threadIdx.x;
    int bm = blockIdx.y * 128;
    int bn = blockIdx.x * 128;
    int lr = tid >> 1;             // 0..127
    int lc = (tid & 1) * 8;        // 0 or 8
    const float* Ap = A + (size_t)(bm + lr) * K + lc;
    const float* Bp = B + (size_t)(bn + lr) * K + lc;
    int tx = tid & 15;             // n dir
    int ty = tid >> 4;             // m dir
    float acc[8][8];
#pragma unroll
    for (int i = 0; i < 8; i++)
#pragma unroll
        for (int j = 0; j < 8; j++) acc[i][j] = 0.f;

    for (int k0 = 0; k0 < K; k0 += 16) {
        float4 a0 = *(const float4*)(Ap + k0);
        float4 a1 = *(const float4*)(Ap + k0 + 4);
        float4 b0 = *(const float4*)(Bp + k0);
        float4 b1 = *(const float4*)(Bp + k0 + 4);
        __syncthreads();
        As[lc + 0][lr] = a0.x; As[lc + 1][lr] = a0.y; As[lc + 2][lr] = a0.z; As[lc + 3][lr] = a0.w;
        As[lc + 4][lr] = a1.x; As[lc + 5][lr] = a1.y; As[lc + 6][lr] = a1.z; As[lc + 7][lr] = a1.w;
        Bs[lc + 0][lr] = b0.x; Bs[lc + 1][lr] = b0.y; Bs[lc + 2][lr] = b0.z; Bs[lc + 3][lr] = b0.w;
        Bs[lc + 4][lr] = b1.x; Bs[lc + 5][lr] = b1.y; Bs[lc + 6][lr] = b1.z; Bs[lc + 7][lr] = b1.w;
        __syncthreads();
#pragma unroll
        for (int kk = 0; kk < 16; kk++) {
            float a[8], b[8];
            *(float4*)(a)     = *(const float4*)&As[kk][ty * 8];
            *(float4*)(a + 4) = *(const float4*)&As[kk][ty * 8 + 4];
            *(float4*)(b)     = *(const float4*)&Bs[kk][tx * 8];
            *(float4*)(b + 4) = *(const float4*)&Bs[kk][tx * 8 + 4];
#pragma unroll
            for (int i = 0; i < 8; i++)
#pragma unroll
                for (int j = 0; j < 8; j++) acc[i][j] += a[i] * b[j];
        }
    }

#pragma unroll
    for (int i = 0; i < 8; i++) {
        int row = bm + ty * 8 + i;
#pragma unroll
        for (int j = 0; j < 8; j += 4) {
            int col = bn + tx * 8 + j;
            float4 r;
            r.x = acc[i][j + 0]; r.y = acc[i][j + 1]; r.z = acc[i][j + 2]; r.w = acc[i][j + 3];
            if (bias) {
                r.x += bias[col + 0]; r.y += bias[col + 1]; r.z += bias[col + 2]; r.w += bias[col + 3];
            }
            size_t idx = (size_t)row * N + col;
            if (res) {
                float4 rr = *(const float4*)(res + idx);
                r.x += rr.x; r.y += rr.y; r.z += rr.z; r.w += rr.w;
            }
            *(float4*)(C + idx) = r;
        }
    }
}

// ---------------- flash attention (fp32, causal, GQA) ----------------
// grid: (qtile=32, head=32), block 256, dyn smem: Qs/Ks/Vs 64x128 + Ps 64x64
#define BQT 64
#define BKT 64
__global__ void __launch_bounds__(256, 1)
attn_kernel(const float* __restrict__ q, const float* __restrict__ k,
            const float* __restrict__ v, const float* __restrict__ amask,
            float* __restrict__ out) {
    extern __shared__ float sm[];
    float* Qs = sm;                      // 64*128
    float* Ks = Qs + BQT * DH;           // 64*128
    float* Vs = Ks + BKT * DH;           // 64*128
    float* Ps = Vs + BKT * DH;           // 64*64

    int qt = blockIdx.x;
    int h  = blockIdx.y;
    int kvh = h >> 2;                    // n_rep = 4
    int tid = threadIdx.x;
    int r  = tid >> 2;                   // 0..63  (query row in tile)
    int cq = tid & 3;                    // quad lane

    const float* qbase = q + (size_t)(qt * BQT) * NH * DH + h * DH;
    for (int i = tid; i < BQT * DH / 4; i += 256) {
        int rr = i >> 5;          // /32
        int dd = (i & 31) * 4;
        *(float4*)&Qs[rr * DH + dd] = *(const float4*)&qbase[(size_t)rr * NH * DH + dd];
    }

    float m = NEGF, l = 0.f;
    float acc[32];
#pragma unroll
    for (int j = 0; j < 32; j++) acc[j] = 0.f;

    const float scale = 0.08838834764831845f;   // 1/sqrt(128)

    for (int kt = 0; kt <= qt; kt++) {
        __syncthreads();   // protect Ks/Vs/Ps reuse
        const float* kbase = k + (size_t)(kt * BKT) * NKV * DH + kvh * DH;
        const float* vbase = v + (size_t)(kt * BKT) * NKV * DH + kvh * DH;
        for (int i = tid; i < BKT * DH / 4; i += 256) {
            int rr = i >> 5;
            int dd = (i & 31) * 4;
            *(float4*)&Ks[rr * DH + dd] = *(const float4*)&kbase[(size_t)rr * NKV * DH + dd];
            *(float4*)&Vs[rr * DH + dd] = *(const float4*)&vbase[(size_t)rr * NKV * DH + dd];
        }
        __syncthreads();

        // S = Q K^T for my 16 columns
        float s[16];
#pragma unroll
        for (int cc = 0; cc < 16; cc++) s[cc] = 0.f;
        const float* qrow = &Qs[r * DH];
#pragma unroll 4
        for (int d0 = 0; d0 < DH; d0 += 16) {
            float4 q0 = *(const float4*)&qrow[d0];
            float4 q1 = *(const float4*)&qrow[d0 + 4];
            float4 q2 = *(const float4*)&qrow[d0 + 8];
            float4 q3 = *(const float4*)&qrow[d0 + 12];
#pragma unroll
            for (int cc = 0; cc < 16; cc++) {
                const float* krow = &Ks[(cc * 4 + cq) * DH + d0];
                float4 k0 = *(const float4*)&krow[0];
                float4 k1 = *(const float4*)&krow[4];
                float4 k2 = *(const float4*)&krow[8];
                float4 k3 = *(const float4*)&krow[12];
                s[cc] += q0.x * k0.x + q0.y * k0.y + q0.z * k0.z + q0.w * k0.w
                       + q1.x * k1.x + q1.y * k1.y + q1.z * k1.z + q1.w * k1.w
                       + q2.x * k2.x + q2.y * k2.y + q2.z * k2.z + q2.w * k2.w
                       + q3.x * k3.x + q3.y * k3.y + q3.z * k3.z + q3.w * k3.w;
            }
        }

        int qi = qt * BQT + r;
        float tmax = NEGF;
#pragma unroll
        for (int cc = 0; cc < 16; cc++) {
            int kj = kt * BKT + cc * 4 + cq;
            float sc = s[cc] * scale;
            if (kj > qi) sc = NEGF;
            else if (amask[kj] <= 0.5f) sc = NEGF;
            s[cc] = sc;
            tmax = fmaxf(tmax, sc);
        }
        tmax = fmaxf(tmax, __shfl_xor_sync(0xffffffffu, tmax, 1));
        tmax = fmaxf(tmax, __shfl_xor_sync(0xffffffffu, tmax, 2));
        float mnew = fmaxf(m, tmax);
        float corr = expf(m - mnew);
        float psum = 0.f;
#pragma unroll
        for (int cc = 0; cc < 16; cc++) {
            float p = expf(s[cc] - mnew);
            Ps[r * 64 + cc * 4 + cq] = p;
            psum += p;
        }
        psum += __shfl_xor_sync(0xffffffffu, psum, 1);
        psum += __shfl_xor_sync(0xffffffffu, psum, 2);
        l = l * corr + psum;
        m = mnew;
#pragma unroll
        for (int j = 0; j < 32; j++) acc[j] *= corr;
        __syncthreads();

        // O += P V  (my d chunk = cq*32 .. +32)
        const float* vb = &Vs[cq * 32];
#pragma unroll 8
        for (int c = 0; c < 64; c++) {
            float pv = Ps[r * 64 + c];
            const float* vrow = vb + c * DH;
#pragma unroll
            for (int j = 0; j < 8; j++) {
                float4 vv = *(const float4*)&vrow[j * 4];
                acc[j * 4 + 0] += pv * vv.x;
                acc[j * 4 + 1] += pv * vv.y;
                acc[j * 4 + 2] += pv * vv.z;
                acc[j * 4 + 3] += pv * vv.w;
            }
        }
    }

    float invl = 1.f / l;
    float* ob = out + (size_t)(qt * BQT + r) * (NH * DH) + h * DH + cq * 32;
#pragma unroll
    for (int j = 0; j < 8; j++) {
        float4 o;
        o.x = acc[j * 4 + 0] * invl;
        o.y = acc[j * 4 + 1] * invl;
        o.z = acc[j * 4 + 2] * invl;
        o.w = acc[j * 4 + 3] * invl;
        *(float4*)&ob[j * 4] = o;
    }
}

// ---------------- launch ----------------
extern "C" void kernel_launch(void* const* d_in, const int* in_sizes, int n_in,
                              void* d_out, int out_size) {
    const float* hidden  = (const float*)d_in[0];
    const float* embeds  = (const float*)d_in[1];
    const float* amask   = (const float*)d_in[2];
    const float* fc_w    = (const float*)d_in[3];
    const float* fc_b    = (const float*)d_in[4];
    const float* in_norm = (const float*)d_in[5];
    const float* q_w     = (const float*)d_in[6];
    const float* k_w     = (const float*)d_in[7];
    const float* v_w     = (const float*)d_in[8];
    const float* o_w     = (const float*)d_in[9];
    const float* post_nw = (const float*)d_in[10];
    const float* gate_w  = (const float*)d_in[11];
    const float* up_w    = (const float*)d_in[12];
    const float* down_w  = (const float*)d_in[13];
    float* out = (float*)d_out;

    float *cat, *x, *hbuf, *qb, *kb, *vb, *attn, *x2, *gate, *up;
    cudaGetSymbolAddress((void**)&cat,  g_cat);
    cudaGetSymbolAddress((void**)&x,    g_x);
    cudaGetSymbolAddress((void**)&hbuf, g_h);
    cudaGetSymbolAddress((void**)&qb,   g_q);
    cudaGetSymbolAddress((void**)&kb,   g_k);
    cudaGetSymbolAddress((void**)&vb,   g_v);
    cudaGetSymbolAddress((void**)&attn, g_attn);
    cudaGetSymbolAddress((void**)&x2,   g_x2);
    cudaGetSymbolAddress((void**)&gate, g_gate);
    cudaGetSymbolAddress((void**)&up,   g_up);

    // concat(embeds, hidden)
    {
        int n4 = SQ * 2 * HD / 4;
        concat_kernel<<<(n4 + 255) / 256, 256>>>(embeds, hidden, cat);
    }
    // fc: x = cat @ fc_w^T + fc_b
    gemm_nt<<<dim3(HD / 128, SQ / 128), 256>>>(cat, fc_w, x, fc_b, nullptr, SQ, HD, 2 * HD);
    // rmsnorm
    rmsnorm_kernel<<<SQ, 256>>>(x, in_norm, hbuf);
    // q/k/v
    gemm_nt<<<dim3(NH * DH / 128, SQ / 128), 256>>>(hbuf, q_w, qb, nullptr, nullptr, SQ, NH * DH, HD);
    gemm_nt<<<dim3(NKV * DH / 128, SQ / 128), 256>>>(hbuf, k_w, kb, nullptr, nullptr, SQ, NKV * DH, HD);
    gemm_nt<<<dim3(NKV * DH / 128, SQ / 128), 256>>>(hbuf, v_w, vb, nullptr, nullptr, SQ, NKV * DH, HD);
    // rope
    rope_kernel<<<SQ * (NH + NKV), DH>>>(qb, kb);
    // attention
    {
        int smem = (3 * BQT * DH + BQT * BKT) * (int)sizeof(float);  // 114688
        cudaFuncSetAttribute(attn_kernel, cudaFuncAttributeMaxDynamicSharedMemorySize, smem);
        attn_kernel<<<dim3(SQ / BQT, NH), 256, smem>>>(qb, kb, vb, amask, attn);
    }
    // o-proj + residual
    gemm_nt<<<dim3(HD / 128, SQ / 128), 256>>>(attn, o_w, x2, nullptr, x, SQ, HD, NH * DH);
    // post norm
    rmsnorm_kernel<<<SQ, 256>>>(x2, post_nw, hbuf);
    // mlp
    gemm_nt<<<dim3(IDIM / 128, SQ / 128), 256>>>(hbuf, gate_w, gate, nullptr, nullptr, SQ, IDIM, HD);
    gemm_nt<<<dim3(IDIM / 128, SQ / 128), 256>>>(hbuf, up_w, up, nullptr, nullptr, SQ, IDIM, HD);
    {
        int n = SQ * IDIM;
        silu_mul_kernel<<<(n + 255) / 256, 256>>>(gate, up, gate, n);
    }
    // down + residual -> out
    gemm_nt<<<dim3(HD / 128, SQ / 128), 256>>>(gate, down_w, out, nullptr, x2, SQ, HD, IDIM);
}

// round 11
// speedup vs baseline: 1.6374x; 1.6374x over previous
#include <cuda_runtime.h>
#include <cuda_bf16.h>
#include <math.h>
#include <stdint.h>

#define SQ 2048
#define HD 4096
#define NH 32
#define NKV 8
#define DH 128
#define IDIM 11008
#define EPSR 1e-6f
#define NEGF -3.0e38f

// ---------------- fp32 scratch ----------------
__device__ float g_cat [SQ * 2 * HD];
__device__ float g_x   [SQ * HD];
__device__ float g_h   [SQ * HD];
__device__ float g_q   [SQ * NH * DH];
__device__ float g_k   [SQ * NKV * DH];
__device__ float g_v   [SQ * NKV * DH];
__device__ float g_attn[SQ * NH * DH];
__device__ float g_x2  [SQ * HD];
__device__ float g_gate[SQ * IDIM];
__device__ float g_up  [SQ * IDIM];

// ---------------- shared bf16 hi/lo scratch (split on demand) ----------------
#define WSCR (IDIM * HD)
#define ASCR (SQ * IDIM)
__device__ __nv_bfloat16 g_wh[WSCR], g_wl[WSCR];
__device__ __nv_bfloat16 g_ah[ASCR], g_al[ASCR];

// ---------------- PTX helpers ----------------
__device__ __forceinline__ uint32_t s2u(const void* p) {
    uint32_t a;
    asm("{ .reg .u64 t; cvta.to.shared.u64 t, %1; cvt.u32.u64 %0, t; }" : "=r"(a) : "l"(p));
    return a;
}
__device__ __forceinline__ void cp16(uint32_t s, const void* g) {
    asm volatile("cp.async.cg.shared.global [%0], [%1], 16;" :: "r"(s), "l"(g));
}
#define CP_COMMIT() asm volatile("cp.async.commit_group;")

__device__ __forceinline__ void ldsm4(uint32_t a[4], uint32_t addr) {
    asm volatile("ldmatrix.sync.aligned.m8n8.x4.shared.b16 {%0,%1,%2,%3}, [%4];"
                 : "=r"(a[0]), "=r"(a[1]), "=r"(a[2]), "=r"(a[3]) : "r"(addr));
}
__device__ __forceinline__ void mma16816(float c[4], const uint32_t a[4], const uint32_t b[2]) {
    asm volatile(
        "mma.sync.aligned.m16n8k16.row.col.f32.bf16.bf16.f32 "
        "{%0,%1,%2,%3}, {%4,%5,%6,%7}, {%8,%9}, {%0,%1,%2,%3};"
        : "+f"(c[0]), "+f"(c[1]), "+f"(c[2]), "+f"(c[3])
        : "r"(a[0]), "r"(a[1]), "r"(a[2]), "r"(a[3]), "r"(b[0]), "r"(b[1]));
}

// ---------------- fp32 -> bf16 hi/lo split ----------------
__global__ void split_bf16(const float* __restrict__ x,
                           __nv_bfloat16* __restrict__ h,
                           __nv_bfloat16* __restrict__ l, int n) {
    int i = (blockIdx.x * blockDim.x + threadIdx.x) * 4;
    if (i >= n) return;
    float4 v = *(const float4*)(x + i);
    __nv_bfloat16 h0 = __float2bfloat16(v.x);
    __nv_bfloat16 h1 = __float2bfloat16(v.y);
    __nv_bfloat16 h2 = __float2bfloat16(v.z);
    __nv_bfloat16 h3 = __float2bfloat16(v.w);
    __nv_bfloat16 l0 = __float2bfloat16(v.x - __bfloat162float(h0));
    __nv_bfloat16 l1 = __float2bfloat16(v.y - __bfloat162float(h1));
    __nv_bfloat16 l2 = __float2bfloat16(v.z - __bfloat162float(h2));
    __nv_bfloat16 l3 = __float2bfloat16(v.w - __bfloat162float(h3));
    __nv_bfloat162 a; a.x = h0; a.y = h1;
    __nv_bfloat162 b; b.x = h2; b.y = h3;
    __nv_bfloat162 c; c.x = l0; c.y = l1;
    __nv_bfloat162 d; d.x = l2; d.y = l3;
    *(__nv_bfloat162*)(h + i)     = a;
    *(__nv_bfloat162*)(h + i + 2) = b;
    *(__nv_bfloat162*)(l + i)     = c;
    *(__nv_bfloat162*)(l + i + 2) = d;
}

// ---------------- HMMA GEMM: C[M,N] = A[M,K]*B[N,K]^T (+bias)(+res), 3-term bf16 ----------------
// CTA 128x128, BK=64, 2-stage cp.async. 8 warps = 2(M) x 4(N), warp tile 64x32.
#define LDS 72                        // smem row stride in bf16 (144B: 16B-aligned, ldmatrix-legal)
#define MATB (128 * LDS * 2)          // 18432 bytes per matrix tile
#define STAGEB (4u * MATB)            // Ah, Al, Bh, Bl

__global__ void __launch_bounds__(256, 1)
gemm_mma(const __nv_bfloat16* __restrict__ Ah, const __nv_bfloat16* __restrict__ Al,
         const __nv_bfloat16* __restrict__ Bh, const __nv_bfloat16* __restrict__ Bl,
         float* __restrict__ C, const float* __restrict__ bias, const float* __restrict__ res,
         int M, int N, int K) {
    extern __shared__ char smem[];
    uint32_t sb = s2u(smem);
    int tid = threadIdx.x;
    int wid = tid >> 5, lane = tid & 31;
    int wm = wid >> 2, wn = wid & 3;
    int bm = blockIdx.y * 128;
    int bn = blockIdx.x * 128;

    float acc[4][4][4];
#pragma unroll
    for (int i = 0; i < 4; i++)
#pragma unroll
        for (int j = 0; j < 4; j++)
#pragma unroll
            for (int t = 0; t < 4; t++) acc[i][j][t] = 0.f;

#define LOADC(c) do { \
        uint32_t st = sb + (uint32_t)((c) & 1) * STAGEB; \
        int k0 = (c) << 6; \
        _Pragma("unroll") \
        for (int it = 0; it < 4; it++) { \
            int idx = tid + it * 256; \
            int row = idx >> 3, col = (idx & 7) * 8; \
            uint32_t so = (uint32_t)(row * LDS + col) * 2; \
            size_t ga = (size_t)(bm + row) * K + k0 + col; \
            size_t gb = (size_t)(bn + row) * K + k0 + col; \
            cp16(st + so,            Ah + ga); \
            cp16(st + MATB + so,     Al + ga); \
            cp16(st + 2 * MATB + so, Bh + gb); \
            cp16(st + 3 * MATB + so, Bl + gb); \
        } \
        CP_COMMIT(); \
    } while (0)

    int nc = K >> 6;
    LOADC(0);

    for (int c = 0; c < nc; c++) {
        if (c + 1 < nc) {
            LOADC(c + 1);
            asm volatile("cp.async.wait_group 1;");
        } else {
            asm volatile("cp.async.wait_group 0;");
        }
        __syncthreads();

        uint32_t sA = sb + (uint32_t)(c & 1) * STAGEB;
        uint32_t sB = sA + 2 * MATB;
        int arow = wm * 64 + (lane & 15);
        int brow = wn * 32 + (lane & 15);
        int koff = ((lane >> 4) & 1) * 8;

#pragma unroll
        for (int k16 = 0; k16 < 64; k16 += 16) {
            uint32_t ah[4][4], al[4][4], bh[4][2], bl[4][2];
#pragma unroll
            for (int i = 0; i < 4; i++) {
                uint32_t ad = sA + (uint32_t)((arow + i * 16) * LDS + k16 + koff) * 2;
                ldsm4(ah[i], ad);
                ldsm4(al[i], ad + MATB);
            }
#pragma unroll
            for (int j2 = 0; j2 < 2; j2++) {
                uint32_t bd = sB + (uint32_t)((brow + j2 * 16) * LDS + k16 + koff) * 2;
                uint32_t t[4];
                // ldmatrix.x4 returns: t0=(n0-7,k0-7) t1=(n8-15,k0-7) t2=(n0-7,k8-15) t3=(n8-15,k8-15)
                // mma B-frag per n8 group = { (n,k0-7), (n,k8-15) }  ->  {t0,t2} and {t1,t3}
                ldsm4(t, bd);
                bh[j2 * 2][0]     = t[0]; bh[j2 * 2][1]     = t[2];
                bh[j2 * 2 + 1][0] = t[1]; bh[j2 * 2 + 1][1] = t[3];
                ldsm4(t, bd + MATB);
                bl[j2 * 2][0]     = t[0]; bl[j2 * 2][1]     = t[2];
                bl[j2 * 2 + 1][0] = t[1]; bl[j2 * 2 + 1][1] = t[3];
            }
#pragma unroll
            for (int i = 0; i < 4; i++)
#pragma unroll
                for (int j = 0; j < 4; j++) {
                    mma16816(acc[i][j], ah[i], bh[j]);
                    mma16816(acc[i][j], ah[i], bl[j]);
                    mma16816(acc[i][j], al[i], bh[j]);
                }
        }
        __syncthreads();
    }

    // epilogue
    int tr = lane >> 2, tc = (lane & 3) * 2;
    int r0 = bm + wm * 64;
    int c0 = bn + wn * 32;
#pragma unroll
    for (int i = 0; i < 4; i++) {
#pragma unroll
        for (int j = 0; j < 4; j++) {
            int grow = r0 + i * 16 + tr;
            int gcol = c0 + j * 8 + tc;
            float2 v0, v1;
            v0.x = acc[i][j][0]; v0.y = acc[i][j][1];
            v1.x = acc[i][j][2]; v1.y = acc[i][j][3];
            if (bias) {
                float b0 = bias[gcol], b1 = bias[gcol + 1];
                v0.x += b0; v0.y += b1;
                v1.x += b0; v1.y += b1;
            }
            size_t i0 = (size_t)grow * N + gcol;
            size_t i1 = (size_t)(grow + 8) * N + gcol;
            if (res) {
                float2 r0v = *(const float2*)(res + i0);
                float2 r1v = *(const float2*)(res + i1);
                v0.x += r0v.x; v0.y += r0v.y;
                v1.x += r1v.x; v1.y += r1v.y;
            }
            *(float2*)(C + i0) = v0;
            *(float2*)(C + i1) = v1;
        }
    }
}

// ---------------- concat ----------------
__global__ void concat_kernel(const float* __restrict__ embeds,
                              const float* __restrict__ hidden,
                              float* __restrict__ out) {
    int t = blockIdx.x * blockDim.x + threadIdx.x;
    int e = t * 4;
    if (e >= SQ * 2 * HD) return;
    int s = e >> 13;
    int i = e & 8191;
    const float* src = (i < HD) ? (embeds + s * HD + i) : (hidden + s * HD + (i - HD));
    *(float4*)(out + e) = *(const float4*)src;
}

// ---------------- rmsnorm ----------------
__global__ void rmsnorm_kernel(const float* __restrict__ x,
                               const float* __restrict__ w,
                               float* __restrict__ out) {
    int row = blockIdx.x;
    const float* xr = x + (size_t)row * HD;
    float ss = 0.f;
    for (int i = threadIdx.x; i < HD; i += 256) { float v = xr[i]; ss += v * v; }
    __shared__ float red[256];
    red[threadIdx.x] = ss;
    __syncthreads();
    for (int o = 128; o > 0; o >>= 1) {
        if (threadIdx.x < o) red[threadIdx.x] += red[threadIdx.x + o];
        __syncthreads();
    }
    float scale = rsqrtf(red[0] / (float)HD + EPSR);
    for (int i = threadIdx.x; i < HD; i += 256)
        out[(size_t)row * HD + i] = xr[i] * scale * w[i];
}

// ---------------- rope ----------------
__global__ void rope_kernel(float* __restrict__ q, float* __restrict__ k) {
    int b = blockIdx.x;
    int s = b / (NH + NKV);
    int h = b - s * (NH + NKV);
    float* ptr = (h < NH) ? (q + ((size_t)s * NH + h) * DH)
                          : (k + ((size_t)s * NKV + (h - NH)) * DH);
    int d = threadIdx.x;
    __shared__ float row[DH];
    row[d] = ptr[d];
    __syncthreads();
    int j = d & 63;
    double invf = pow(10000.0, -(double)j / 64.0);
    float ang = (float)((double)s * invf);
    float c  = (float)cos((double)ang);
    float sn = (float)sin((double)ang);
    float rot = (d < 64) ? -row[d + 64] : row[d - 64];
    ptr[d] = row[d] * c + rot * sn;
}

// ---------------- silu(gate) * up ----------------
__global__ void silu_mul_kernel(const float* __restrict__ g,
                                const float* __restrict__ u,
                                float* __restrict__ out, int n) {
    int i = blockIdx.x * blockDim.x + threadIdx.x;
    if (i < n) {
        float x = g[i];
        float s = x / (1.f + expf(-x));
        out[i] = s * u[i];
    }
}

// ---------------- flash attention (fp32, causal, GQA) ----------------
#define BQT 64
#define BKT 64
__global__ void __launch_bounds__(256, 1)
attn_kernel(const float* __restrict__ q, const float* __restrict__ k,
            const float* __restrict__ v, const float* __restrict__ amask,
            float* __restrict__ out) {
    extern __shared__ float sm[];
    float* Qs = sm;
    float* Ks = Qs + BQT * DH;
    float* Vs = Ks + BKT * DH;
    float* Ps = Vs + BKT * DH;

    int qt = blockIdx.x;
    int h  = blockIdx.y;
    int kvh = h >> 2;
    int tid = threadIdx.x;
    int r  = tid >> 2;
    int cq = tid & 3;

    const float* qbase = q + (size_t)(qt * BQT) * NH * DH + h * DH;
    for (int i = tid; i < BQT * DH / 4; i += 256) {
        int rr = i >> 5;
        int dd = (i & 31) * 4;
        *(float4*)&Qs[rr * DH + dd] = *(const float4*)&qbase[(size_t)rr * NH * DH + dd];
    }

    float m = NEGF, l = 0.f;
    float acc[32];
#pragma unroll
    for (int j = 0; j < 32; j++) acc[j] = 0.f;

    const float scale = 0.08838834764831845f;

    for (int kt = 0; kt <= qt; kt++) {
        __syncthreads();
        const float* kbase = k + (size_t)(kt * BKT) * NKV * DH + kvh * DH;
        const float* vbase = v + (size_t)(kt * BKT) * NKV * DH + kvh * DH;
        for (int i = tid; i < BKT * DH / 4; i += 256) {
            int rr = i >> 5;
            int dd = (i & 31) * 4;
            *(float4*)&Ks[rr * DH + dd] = *(const float4*)&kbase[(size_t)rr * NKV * DH + dd];
            *(float4*)&Vs[rr * DH + dd] = *(const float4*)&vbase[(size_t)rr * NKV * DH + dd];
        }
        __syncthreads();

        float s[16];
#pragma unroll
        for (int cc = 0; cc < 16; cc++) s[cc] = 0.f;
        const float* qrow = &Qs[r * DH];
#pragma unroll 4
        for (int d0 = 0; d0 < DH; d0 += 16) {
            float4 q0 = *(const float4*)&qrow[d0];
            float4 q1 = *(const float4*)&qrow[d0 + 4];
            float4 q2 = *(const float4*)&qrow[d0 + 8];
            float4 q3 = *(const float4*)&qrow[d0 + 12];
#pragma unroll
            for (int cc = 0; cc < 16; cc++) {
                const float* krow = &Ks[(cc * 4 + cq) * DH + d0];
                float4 k0 = *(const float4*)&krow[0];
                float4 k1 = *(const float4*)&krow[4];
                float4 k2 = *(const float4*)&krow[8];
                float4 k3 = *(const float4*)&krow[12];
                s[cc] += q0.x * k0.x + q0.y * k0.y + q0.z * k0.z + q0.w * k0.w
                       + q1.x * k1.x + q1.y * k1.y + q1.z * k1.z + q1.w * k1.w
                       + q2.x * k2.x + q2.y * k2.y + q2.z * k2.z + q2.w * k2.w
                       + q3.x * k3.x + q3.y * k3.y + q3.z * k3.z + q3.w * k3.w;
            }
        }

        int qi = qt * BQT + r;
        float tmax = NEGF;
#pragma unroll
        for (int cc = 0; cc < 16; cc++) {
            int kj = kt * BKT + cc * 4 + cq;
            float sc = s[cc] * scale;
            if (kj > qi) sc = NEGF;
            else if (amask[kj] <= 0.5f) sc = NEGF;
            s[cc] = sc;
            tmax = fmaxf(tmax, sc);
        }
        tmax = fmaxf(tmax, __shfl_xor_sync(0xffffffffu, tmax, 1));
        tmax = fmaxf(tmax, __shfl_xor_sync(0xffffffffu, tmax, 2));
        float mnew = fmaxf(m, tmax);
        float corr = expf(m - mnew);
        float psum = 0.f;
#pragma unroll
        for (int cc = 0; cc < 16; cc++) {
            float p = expf(s[cc] - mnew);
            Ps[r * 64 + cc * 4 + cq] = p;
            psum += p;
        }
        psum += __shfl_xor_sync(0xffffffffu, psum, 1);
        psum += __shfl_xor_sync(0xffffffffu, psum, 2);
        l = l * corr + psum;
        m = mnew;
#pragma unroll
        for (int j = 0; j < 32; j++) acc[j] *= corr;
        __syncthreads();

        const float* vb = &Vs[cq * 32];
#pragma unroll 8
        for (int c = 0; c < 64; c++) {
            float pv = Ps[r * 64 + c];
            const float* vrow = vb + c * DH;
#pragma unroll
            for (int j = 0; j < 8; j++) {
                float4 vv = *(const float4*)&vrow[j * 4];
                acc[j * 4 + 0] += pv * vv.x;
                acc[j * 4 + 1] += pv * vv.y;
                acc[j * 4 + 2] += pv * vv.z;
                acc[j * 4 + 3] += pv * vv.w;
            }
        }
    }

    float invl = 1.f / l;
    float* ob = out + (size_t)(qt * BQT + r) * (NH * DH) + h * DH + cq * 32;
#pragma unroll
    for (int j = 0; j < 8; j++) {
        float4 o;
        o.x = acc[j * 4 + 0] * invl;
        o.y = acc[j * 4 + 1] * invl;
        o.z = acc[j * 4 + 2] * invl;
        o.w = acc[j * 4 + 3] * invl;
        *(float4*)&ob[j * 4] = o;
    }
}

// ---------------- launch ----------------
static void do_split(const float* src, __nv_bfloat16* h, __nv_bfloat16* l, int n) {
    split_bf16<<<(n / 4 + 255) / 256, 256>>>(src, h, l, n);
}

extern "C" void kernel_launch(void* const* d_in, const int* in_sizes, int n_in,
                              void* d_out, int out_size) {
    const float* hidden  = (const float*)d_in[0];
    const float* embeds  = (const float*)d_in[1];
    const float* amask   = (const float*)d_in[2];
    const float* fc_w    = (const float*)d_in[3];
    const float* fc_b    = (const float*)d_in[4];
    const float* in_norm = (const float*)d_in[5];
    const float* q_w     = (const float*)d_in[6];
    const float* k_w     = (const float*)d_in[7];
    const float* v_w     = (const float*)d_in[8];
    const float* o_w     = (const float*)d_in[9];
    const float* post_nw = (const float*)d_in[10];
    const float* gate_w  = (const float*)d_in[11];
    const float* up_w    = (const float*)d_in[12];
    const float* down_w  = (const float*)d_in[13];
    float* out = (float*)d_out;

    float *cat, *x, *hbuf, *qb, *kb, *vb, *attn, *x2, *gate, *up;
    cudaGetSymbolAddress((void**)&cat,  g_cat);
    cudaGetSymbolAddress((void**)&x,    g_x);
    cudaGetSymbolAddress((void**)&hbuf, g_h);
    cudaGetSymbolAddress((void**)&qb,   g_q);
    cudaGetSymbolAddress((void**)&kb,   g_k);
    cudaGetSymbolAddress((void**)&vb,   g_v);
    cudaGetSymbolAddress((void**)&attn, g_attn);
    cudaGetSymbolAddress((void**)&x2,   g_x2);
    cudaGetSymbolAddress((void**)&gate, g_gate);
    cudaGetSymbolAddress((void**)&up,   g_up);

    __nv_bfloat16 *wh, *wl, *ah, *al;
    cudaGetSymbolAddress((void**)&wh, g_wh);
    cudaGetSymbolAddress((void**)&wl, g_wl);
    cudaGetSymbolAddress((void**)&ah, g_ah);
    cudaGetSymbolAddress((void**)&al, g_al);

    int gsmem = 2 * (int)STAGEB;   // 147456
    cudaFuncSetAttribute(gemm_mma, cudaFuncAttributeMaxDynamicSharedMemorySize, gsmem);
    int asmem = (3 * BQT * DH + BQT * BKT) * (int)sizeof(float);
    cudaFuncSetAttribute(attn_kernel, cudaFuncAttributeMaxDynamicSharedMemorySize, asmem);

    // concat + split A
    {
        int n4 = SQ * 2 * HD / 4;
        concat_kernel<<<(n4 + 255) / 256, 256>>>(embeds, hidden, cat);
    }
    do_split(cat, ah, al, SQ * 2 * HD);
    do_split(fc_w, wh, wl, HD * 2 * HD);
    gemm_mma<<<dim3(HD / 128, SQ / 128), 256, gsmem>>>(
        ah, al, wh, wl, x, fc_b, nullptr, SQ, HD, 2 * HD);

    // in-norm + split
    rmsnorm_kernel<<<SQ, 256>>>(x, in_norm, hbuf);
    do_split(hbuf, ah, al, SQ * HD);

    // q/k/v
    do_split(q_w, wh, wl, HD * HD);
    gemm_mma<<<dim3(NH * DH / 128, SQ / 128), 256, gsmem>>>(
        ah, al, wh, wl, qb, nullptr, nullptr, SQ, NH * DH, HD);
    do_split(k_w, wh, wl, NKV * DH * HD);
    gemm_mma<<<dim3(NKV * DH / 128, SQ / 128), 256, gsmem>>>(
        ah, al, wh, wl, kb, nullptr, nullptr, SQ, NKV * DH, HD);
    do_split(v_w, wh, wl, NKV * DH * HD);
    gemm_mma<<<dim3(NKV * DH / 128, SQ / 128), 256, gsmem>>>(
        ah, al, wh, wl, vb, nullptr, nullptr, SQ, NKV * DH, HD);

    // rope
    rope_kernel<<<SQ * (NH + NKV), DH>>>(qb, kb);

    // attention
    attn_kernel<<<dim3(SQ / BQT, NH), 256, asmem>>>(qb, kb, vb, amask, attn);

    // o-proj + residual
    do_split(attn, ah, al, SQ * HD);
    do_split(o_w, wh, wl, HD * HD);
    gemm_mma<<<dim3(HD / 128, SQ / 128), 256, gsmem>>>(
        ah, al, wh, wl, x2, nullptr, x, SQ, HD, NH * DH);

    // post-norm + split
    rmsnorm_kernel<<<SQ, 256>>>(x2, post_nw, hbuf);
    do_split(hbuf, ah, al, SQ * HD);

    // mlp
    do_split(gate_w, wh, wl, IDIM * HD);
    gemm_mma<<<dim3(IDIM / 128, SQ / 128), 256, gsmem>>>(
        ah, al, wh, wl, gate, nullptr, nullptr, SQ, IDIM, HD);
    do_split(up_w, wh, wl, IDIM * HD);
    gemm_mma<<<dim3(IDIM / 128, SQ / 128), 256, gsmem>>>(
        ah, al, wh, wl, up, nullptr, nullptr, SQ, IDIM, HD);
    {
        int n = SQ * IDIM;
        silu_mul_kernel<<<(n + 255) / 256, 256>>>(gate, up, gate, n);
    }
    do_split(gate, ah, al, SQ * IDIM);
    do_split(down_w, wh, wl, HD * IDIM);
    gemm_mma<<<dim3(HD / 128, SQ / 128), 256, gsmem>>>(
        ah, al, wh, wl, out, nullptr, x2, SQ, HD, IDIM);
}

// round 14
// speedup vs baseline: 1.6445x; 1.0043x over previous
#include <cuda_runtime.h>
#include <cuda_bf16.h>
#include <math.h>
#include <stdint.h>

#define SQ 2048
#define HD 4096
#define NH 32
#define NKV 8
#define DH 128
#define IDIM 11008
#define EPSR 1e-6f
#define NEGF -3.0e38f

// ---------------- fp32 scratch ----------------
__device__ float g_cat [SQ * 2 * HD];
__device__ float g_x   [SQ * HD];
__device__ float g_h   [SQ * HD];
__device__ float g_q   [SQ * NH * DH];
__device__ float g_k   [SQ * NKV * DH];
__device__ float g_v   [SQ * NKV * DH];
__device__ float g_attn[SQ * NH * DH];
__device__ float g_x2  [SQ * HD];
__device__ float g_gate[SQ * IDIM];
__device__ float g_up  [SQ * IDIM];

// ---------------- shared bf16 hi/lo scratch (split on demand) ----------------
#define WSCR (IDIM * HD)
#define ASCR (SQ * IDIM)
__device__ __nv_bfloat16 g_wh[WSCR], g_wl[WSCR];
__device__ __nv_bfloat16 g_ah[ASCR], g_al[ASCR];

// ---------------- PTX helpers ----------------
__device__ __forceinline__ uint32_t s2u(const void* p) {
    uint32_t a;
    asm("{ .reg .u64 t; cvta.to.shared.u64 t, %1; cvt.u32.u64 %0, t; }" : "=r"(a) : "l"(p));
    return a;
}
__device__ __forceinline__ void cp16(uint32_t s, const void* g) {
    asm volatile("cp.async.cg.shared.global [%0], [%1], 16;" :: "r"(s), "l"(g));
}
#define CP_COMMIT() asm volatile("cp.async.commit_group;")

__device__ __forceinline__ void ldsm4(uint32_t a[4], uint32_t addr) {
    asm volatile("ldmatrix.sync.aligned.m8n8.x4.shared.b16 {%0,%1,%2,%3}, [%4];"
                 : "=r"(a[0]), "=r"(a[1]), "=r"(a[2]), "=r"(a[3]) : "r"(addr));
}
__device__ __forceinline__ void mma16816(float c[4], const uint32_t a[4], const uint32_t b[2]) {
    asm volatile(
        "mma.sync.aligned.m16n8k16.row.col.f32.bf16.bf16.f32 "
        "{%0,%1,%2,%3}, {%4,%5,%6,%7}, {%8,%9}, {%0,%1,%2,%3};"
        : "+f"(c[0]), "+f"(c[1]), "+f"(c[2]), "+f"(c[3])
        : "r"(a[0]), "r"(a[1]), "r"(a[2]), "r"(a[3]), "r"(b[0]), "r"(b[1]));
}

// ---------------- fp32 -> bf16 hi/lo split ----------------
__global__ void split_bf16(const float* __restrict__ x,
                           __nv_bfloat16* __restrict__ h,
                           __nv_bfloat16* __restrict__ l, int n) {
    int i = (blockIdx.x * blockDim.x + threadIdx.x) * 4;
    if (i >= n) return;
    float4 v = *(const float4*)(x + i);
    __nv_bfloat16 h0 = __float2bfloat16(v.x);
    __nv_bfloat16 h1 = __float2bfloat16(v.y);
    __nv_bfloat16 h2 = __float2bfloat16(v.z);
    __nv_bfloat16 h3 = __float2bfloat16(v.w);
    __nv_bfloat16 l0 = __float2bfloat16(v.x - __bfloat162float(h0));
    __nv_bfloat16 l1 = __float2bfloat16(v.y - __bfloat162float(h1));
    __nv_bfloat16 l2 = __float2bfloat16(v.z - __bfloat162float(h2));
    __nv_bfloat16 l3 = __float2bfloat16(v.w - __bfloat162float(h3));
    __nv_bfloat162 a; a.x = h0; a.y = h1;
    __nv_bfloat162 b; b.x = h2; b.y = h3;
    __nv_bfloat162 c; c.x = l0; c.y = l1;
    __nv_bfloat162 d; d.x = l2; d.y = l3;
    *(__nv_bfloat162*)(h + i)     = a;
    *(__nv_bfloat162*)(h + i + 2) = b;
    *(__nv_bfloat162*)(l + i)     = c;
    *(__nv_bfloat162*)(l + i + 2) = d;
}

// ---------------- HMMA GEMM: C[M,N] = A[M,K]*B[N,K]^T (+bias)(+res), 3-term bf16 ----------------
// CTA 128x128, BK=64, 2-stage cp.async. 16 warps = 4(M) x 4(N), warp tile 32x32.
#define LDS 72                        // smem row stride in bf16 (144B: 16B-aligned, ldmatrix-legal)
#define MATB (128 * LDS * 2)          // 18432 bytes per matrix tile
#define STAGEB (4u * MATB)            // Ah, Al, Bh, Bl

__global__ void __launch_bounds__(512, 1)
gemm_mma(const __nv_bfloat16* __restrict__ Ah, const __nv_bfloat16* __restrict__ Al,
         const __nv_bfloat16* __restrict__ Bh, const __nv_bfloat16* __restrict__ Bl,
         float* __restrict__ C, const float* __restrict__ bias, const float* __restrict__ res,
         int M, int N, int K) {
    extern __shared__ char smem[];
    uint32_t sb = s2u(smem);
    int tid = threadIdx.x;
    int wid = tid >> 5, lane = tid & 31;
    int wm = wid >> 2, wn = wid & 3;          // 4x4 warp grid, warp tile 32x32
    int bm = blockIdx.y * 128;
    int bn = blockIdx.x * 128;

    float acc[2][4][4];
#pragma unroll
    for (int i = 0; i < 2; i++)
#pragma unroll
        for (int j = 0; j < 4; j++)
#pragma unroll
            for (int t = 0; t < 4; t++) acc[i][j][t] = 0.f;

#define LOADC(c) do { \
        uint32_t st = sb + (uint32_t)((c) & 1) * STAGEB; \
        int k0 = (c) << 6; \
        _Pragma("unroll") \
        for (int it = 0; it < 2; it++) { \
            int idx = tid + it * 512; \
            int row = idx >> 3, col = (idx & 7) * 8; \
            uint32_t so = (uint32_t)(row * LDS + col) * 2; \
            size_t ga = (size_t)(bm + row) * K + k0 + col; \
            size_t gb = (size_t)(bn + row) * K + k0 + col; \
            cp16(st + so,            Ah + ga); \
            cp16(st + MATB + so,     Al + ga); \
            cp16(st + 2 * MATB + so, Bh + gb); \
            cp16(st + 3 * MATB + so, Bl + gb); \
        } \
        CP_COMMIT(); \
    } while (0)

    int nc = K >> 6;
    LOADC(0);

    for (int c = 0; c < nc; c++) {
        if (c + 1 < nc) {
            LOADC(c + 1);
            asm volatile("cp.async.wait_group 1;");
        } else {
            asm volatile("cp.async.wait_group 0;");
        }
        __syncthreads();

        uint32_t sA = sb + (uint32_t)(c & 1) * STAGEB;
        uint32_t sB = sA + 2 * MATB;
        int arow = wm * 32 + (lane & 15);
        int brow = wn * 32 + (lane & 15);
        int koff = ((lane >> 4) & 1) * 8;

#pragma unroll
        for (int k16 = 0; k16 < 64; k16 += 16) {
            uint32_t ah[2][4], al[2][4], bh[4][2], bl[4][2];
#pragma unroll
            for (int i = 0; i < 2; i++) {
                uint32_t ad = sA + (uint32_t)((arow + i * 16) * LDS + k16 + koff) * 2;
                ldsm4(ah[i], ad);
                ldsm4(al[i], ad + MATB);
            }
#pragma unroll
            for (int j2 = 0; j2 < 2; j2++) {
                uint32_t bd = sB + (uint32_t)((brow + j2 * 16) * LDS + k16 + koff) * 2;
                uint32_t t[4];
                // ldmatrix.x4: t0=(n0-7,k0-7) t1=(n8-15,k0-7) t2=(n0-7,k8-15) t3=(n8-15,k8-15)
                ldsm4(t, bd);
                bh[j2 * 2][0]     = t[0]; bh[j2 * 2][1]     = t[2];
                bh[j2 * 2 + 1][0] = t[1]; bh[j2 * 2 + 1][1] = t[3];
                ldsm4(t, bd + MATB);
                bl[j2 * 2][0]     = t[0]; bl[j2 * 2][1]     = t[2];
                bl[j2 * 2 + 1][0] = t[1]; bl[j2 * 2 + 1][1] = t[3];
            }
#pragma unroll
            for (int i = 0; i < 2; i++)
#pragma unroll
                for (int j = 0; j < 4; j++) {
                    mma16816(acc[i][j], ah[i], bh[j]);
                    mma16816(acc[i][j], ah[i], bl[j]);
                    mma16816(acc[i][j], al[i], bh[j]);
                }
        }
        __syncthreads();
    }

    // epilogue
    int tr = lane >> 2, tc = (lane & 3) * 2;
    int r0 = bm + wm * 32;
    int c0 = bn + wn * 32;
#pragma unroll
    for (int i = 0; i < 2; i++) {
#pragma unroll
        for (int j = 0; j < 4; j++) {
            int grow = r0 + i * 16 + tr;
            int gcol = c0 + j * 8 + tc;
            float2 v0, v1;
            v0.x = acc[i][j][0]; v0.y = acc[i][j][1];
            v1.x = acc[i][j][2]; v1.y = acc[i][j][3];
            if (bias) {
                float b0 = bias[gcol], b1 = bias[gcol + 1];
                v0.x += b0; v0.y += b1;
                v1.x += b0; v1.y += b1;
            }
            size_t i0 = (size_t)grow * N + gcol;
            size_t i1 = (size_t)(grow + 8) * N + gcol;
            if (res) {
                float2 r0v = *(const float2*)(res + i0);
                float2 r1v = *(const float2*)(res + i1);
                v0.x += r0v.x; v0.y += r0v.y;
                v1.x += r1v.x; v1.y += r1v.y;
            }
            *(float2*)(C + i0) = v0;
            *(float2*)(C + i1) = v1;
        }
    }
}

// ---------------- concat ----------------
__global__ void concat_kernel(const float* __restrict__ embeds,
                              const float* __restrict__ hidden,
                              float* __restrict__ out) {
    int t = blockIdx.x * blockDim.x + threadIdx.x;
    int e = t * 4;
    if (e >= SQ * 2 * HD) return;
    int s = e >> 13;
    int i = e & 8191;
    const float* src = (i < HD) ? (embeds + s * HD + i) : (hidden + s * HD + (i - HD));
    *(float4*)(out + e) = *(const float4*)src;
}

// ---------------- rmsnorm ----------------
__global__ void rmsnorm_kernel(const float* __restrict__ x,
                               const float* __restrict__ w,
                               float* __restrict__ out) {
    int row = blockIdx.x;
    const float* xr = x + (size_t)row * HD;
    float ss = 0.f;
    for (int i = threadIdx.x; i < HD; i += 256) { float v = xr[i]; ss += v * v; }
    __shared__ float red[256];
    red[threadIdx.x] = ss;
    __syncthreads();
    for (int o = 128; o > 0; o >>= 1) {
        if (threadIdx.x < o) red[threadIdx.x] += red[threadIdx.x + o];
        __syncthreads();
    }
    float scale = rsqrtf(red[0] / (float)HD + EPSR);
    for (int i = threadIdx.x; i < HD; i += 256)
        out[(size_t)row * HD + i] = xr[i] * scale * w[i];
}

// ---------------- rope ----------------
__global__ void rope_kernel(float* __restrict__ q, float* __restrict__ k) {
    int b = blockIdx.x;
    int s = b / (NH + NKV);
    int h = b - s * (NH + NKV);
    float* ptr = (h < NH) ? (q + ((size_t)s * NH + h) * DH)
                          : (k + ((size_t)s * NKV + (h - NH)) * DH);
    int d = threadIdx.x;
    __shared__ float row[DH];
    row[d] = ptr[d];
    __syncthreads();
    int j = d & 63;
    double invf = pow(10000.0, -(double)j / 64.0);
    float ang = (float)((double)s * invf);
    float c  = (float)cos((double)ang);
    float sn = (float)sin((double)ang);
    float rot = (d < 64) ? -row[d + 64] : row[d - 64];
    ptr[d] = row[d] * c + rot * sn;
}

// ---------------- silu(gate) * up ----------------
__global__ void silu_mul_kernel(const float* __restrict__ g,
                                const float* __restrict__ u,
                                float* __restrict__ out, int n) {
    int i = blockIdx.x * blockDim.x + threadIdx.x;
    if (i < n) {
        float x = g[i];
        float s = x / (1.f + expf(-x));
        out[i] = s * u[i];
    }
}

// ---------------- flash attention (fp32, causal, GQA) ----------------
#define BQT 64
#define BKT 64
__global__ void __launch_bounds__(256, 1)
attn_kernel(const float* __restrict__ q, const float* __restrict__ k,
            const float* __restrict__ v, const float* __restrict__ amask,
            float* __restrict__ out) {
    extern __shared__ float sm[];
    float* Qs = sm;
    float* Ks = Qs + BQT * DH;
    float* Vs = Ks + BKT * DH;
    float* Ps = Vs + BKT * DH;

    int qt = blockIdx.x;
    int h  = blockIdx.y;
    int kvh = h >> 2;
    int tid = threadIdx.x;
    int r  = tid >> 2;
    int cq = tid & 3;

    const float* qbase = q + (size_t)(qt * BQT) * NH * DH + h * DH;
    for (int i = tid; i < BQT * DH / 4; i += 256) {
        int rr = i >> 5;
        int dd = (i & 31) * 4;
        *(float4*)&Qs[rr * DH + dd] = *(const float4*)&qbase[(size_t)rr * NH * DH + dd];
    }

    float m = NEGF, l = 0.f;
    float acc[32];
#pragma unroll
    for (int j = 0; j < 32; j++) acc[j] = 0.f;

    const float scale = 0.08838834764831845f;

    for (int kt = 0; kt <= qt; kt++) {
        __syncthreads();
        const float* kbase = k + (size_t)(kt * BKT) * NKV * DH + kvh * DH;
        const float* vbase = v + (size_t)(kt * BKT) * NKV * DH + kvh * DH;
        for (int i = tid; i < BKT * DH / 4; i += 256) {
            int rr = i >> 5;
            int dd = (i & 31) * 4;
            *(float4*)&Ks[rr * DH + dd] = *(const float4*)&kbase[(size_t)rr * NKV * DH + dd];
            *(float4*)&Vs[rr * DH + dd] = *(const float4*)&vbase[(size_t)rr * NKV * DH + dd];
        }
        __syncthreads();

        float s[16];
#pragma unroll
        for (int cc = 0; cc < 16; cc++) s[cc] = 0.f;
        const float* qrow = &Qs[r * DH];
#pragma unroll 4
        for (int d0 = 0; d0 < DH; d0 += 16) {
            float4 q0 = *(const float4*)&qrow[d0];
            float4 q1 = *(const float4*)&qrow[d0 + 4];
            float4 q2 = *(const float4*)&qrow[d0 + 8];
            float4 q3 = *(const float4*)&qrow[d0 + 12];
#pragma unroll
            for (int cc = 0; cc < 16; cc++) {
                const float* krow = &Ks[(cc * 4 + cq) * DH + d0];
                float4 k0 = *(const float4*)&krow[0];
                float4 k1 = *(const float4*)&krow[4];
                float4 k2 = *(const float4*)&krow[8];
                float4 k3 = *(const float4*)&krow[12];
                s[cc] += q0.x * k0.x + q0.y * k0.y + q0.z * k0.z + q0.w * k0.w
                       + q1.x * k1.x + q1.y * k1.y + q1.z * k1.z + q1.w * k1.w
                       + q2.x * k2.x + q2.y * k2.y + q2.z * k2.z + q2.w * k2.w
                       + q3.x * k3.x + q3.y * k3.y + q3.z * k3.z + q3.w * k3.w;
            }
        }

        int qi = qt * BQT + r;
        float tmax = NEGF;
#pragma unroll
        for (int cc = 0; cc < 16; cc++) {
            int kj = kt * BKT + cc * 4 + cq;
            float sc = s[cc] * scale;
            if (kj > qi) sc = NEGF;
            else if (amask[kj] <= 0.5f) sc = NEGF;
            s[cc] = sc;
            tmax = fmaxf(tmax, sc);
        }
        tmax = fmaxf(tmax, __shfl_xor_sync(0xffffffffu, tmax, 1));
        tmax = fmaxf(tmax, __shfl_xor_sync(0xffffffffu, tmax, 2));
        float mnew = fmaxf(m, tmax);
        float corr = expf(m - mnew);
        float psum = 0.f;
#pragma unroll
        for (int cc = 0; cc < 16; cc++) {
            float p = expf(s[cc] - mnew);
            Ps[r * 64 + cc * 4 + cq] = p;
            psum += p;
        }
        psum += __shfl_xor_sync(0xffffffffu, psum, 1);
        psum += __shfl_xor_sync(0xffffffffu, psum, 2);
        l = l * corr + psum;
        m = mnew;
#pragma unroll
        for (int j = 0; j < 32; j++) acc[j] *= corr;
        __syncthreads();

        const float* vb = &Vs[cq * 32];
#pragma unroll 8
        for (int c = 0; c < 64; c++) {
            float pv = Ps[r * 64 + c];
            const float* vrow = vb + c * DH;
#pragma unroll
            for (int j = 0; j < 8; j++) {
                float4 vv = *(const float4*)&vrow[j * 4];
                acc[j * 4 + 0] += pv * vv.x;
                acc[j * 4 + 1] += pv * vv.y;
                acc[j * 4 + 2] += pv * vv.z;
                acc[j * 4 + 3] += pv * vv.w;
            }
        }
    }

    float invl = 1.f / l;
    float* ob = out + (size_t)(qt * BQT + r) * (NH * DH) + h * DH + cq * 32;
#pragma unroll
    for (int j = 0; j < 8; j++) {
        float4 o;
        o.x = acc[j * 4 + 0] * invl;
        o.y = acc[j * 4 + 1] * invl;
        o.z = acc[j * 4 + 2] * invl;
        o.w = acc[j * 4 + 3] * invl;
        *(float4*)&ob[j * 4] = o;
    }
}

// ---------------- launch ----------------
static void do_split(const float* src, __nv_bfloat16* h, __nv_bfloat16* l, int n) {
    split_bf16<<<(n / 4 + 255) / 256, 256>>>(src, h, l, n);
}

extern "C" void kernel_launch(void* const* d_in, const int* in_sizes, int n_in,
                              void* d_out, int out_size) {
    const float* hidden  = (const float*)d_in[0];
    const float* embeds  = (const float*)d_in[1];
    const float* amask   = (const float*)d_in[2];
    const float* fc_w    = (const float*)d_in[3];
    const float* fc_b    = (const float*)d_in[4];
    const float* in_norm = (const float*)d_in[5];
    const float* q_w     = (const float*)d_in[6];
    const float* k_w     = (const float*)d_in[7];
    const float* v_w     = (const float*)d_in[8];
    const float* o_w     = (const float*)d_in[9];
    const float* post_nw = (const float*)d_in[10];
    const float* gate_w  = (const float*)d_in[11];
    const float* up_w    = (const float*)d_in[12];
    const float* down_w  = (const float*)d_in[13];
    float* out = (float*)d_out;

    float *cat, *x, *hbuf, *qb, *kb, *vb, *attn, *x2, *gate, *up;
    cudaGetSymbolAddress((void**)&cat,  g_cat);
    cudaGetSymbolAddress((void**)&x,    g_x);
    cudaGetSymbolAddress((void**)&hbuf, g_h);
    cudaGetSymbolAddress((void**)&qb,   g_q);
    cudaGetSymbolAddress((void**)&kb,   g_k);
    cudaGetSymbolAddress((void**)&vb,   g_v);
    cudaGetSymbolAddress((void**)&attn, g_attn);
    cudaGetSymbolAddress((void**)&x2,   g_x2);
    cudaGetSymbolAddress((void**)&gate, g_gate);
    cudaGetSymbolAddress((void**)&up,   g_up);

    __nv_bfloat16 *wh, *wl, *ah, *al;
    cudaGetSymbolAddress((void**)&wh, g_wh);
    cudaGetSymbolAddress((void**)&wl, g_wl);
    cudaGetSymbolAddress((void**)&ah, g_ah);
    cudaGetSymbolAddress((void**)&al, g_al);

    int gsmem = 2 * (int)STAGEB;   // 147456
    cudaFuncSetAttribute(gemm_mma, cudaFuncAttributeMaxDynamicSharedMemorySize, gsmem);
    int asmem = (3 * BQT * DH + BQT * BKT) * (int)sizeof(float);
    cudaFuncSetAttribute(attn_kernel, cudaFuncAttributeMaxDynamicSharedMemorySize, asmem);

    // concat + split A
    {
        int n4 = SQ * 2 * HD / 4;
        concat_kernel<<<(n4 + 255) / 256, 256>>>(embeds, hidden, cat);
    }
    do_split(cat, ah, al, SQ * 2 * HD);
    do_split(fc_w, wh, wl, HD * 2 * HD);
    gemm_mma<<<dim3(HD / 128, SQ / 128), 512, gsmem>>>(
        ah, al, wh, wl, x, fc_b, nullptr, SQ, HD, 2 * HD);

    // in-norm + split
    rmsnorm_kernel<<<SQ, 256>>>(x, in_norm, hbuf);
    do_split(hbuf, ah, al, SQ * HD);

    // q/k/v
    do_split(q_w, wh, wl, HD * HD);
    gemm_mma<<<dim3(NH * DH / 128, SQ / 128), 512, gsmem>>>(
        ah, al, wh, wl, qb, nullptr, nullptr, SQ, NH * DH, HD);
    do_split(k_w, wh, wl, NKV * DH * HD);
    gemm_mma<<<dim3(NKV * DH / 128, SQ / 128), 512, gsmem>>>(
        ah, al, wh, wl, kb, nullptr, nullptr, SQ, NKV * DH, HD);
    do_split(v_w, wh, wl, NKV * DH * HD);
    gemm_mma<<<dim3(NKV * DH / 128, SQ / 128), 512, gsmem>>>(
        ah, al, wh, wl, vb, nullptr, nullptr, SQ, NKV * DH, HD);

    // rope
    rope_kernel<<<SQ * (NH + NKV), DH>>>(qb, kb);

    // attention
    attn_kernel<<<dim3(SQ / BQT, NH), 256, asmem>>>(qb, kb, vb, amask, attn);

    // o-proj + residual
    do_split(attn, ah, al, SQ * HD);
    do_split(o_w, wh, wl, HD * HD);
    gemm_mma<<<dim3(HD / 128, SQ / 128), 512, gsmem>>>(
        ah, al, wh, wl, x2, nullptr, x, SQ, HD, NH * DH);

    // post-norm + split
    rmsnorm_kernel<<<SQ, 256>>>(x2, post_nw, hbuf);
    do_split(hbuf, ah, al, SQ * HD);

    // mlp
    do_split(gate_w, wh, wl, IDIM * HD);
    gemm_mma<<<dim3(IDIM / 128, SQ / 128), 512, gsmem>>>(
        ah, al, wh, wl, gate, nullptr, nullptr, SQ, IDIM, HD);
    do_split(up_w, wh, wl, IDIM * HD);
    gemm_mma<<<dim3(IDIM / 128, SQ / 128), 512, gsmem>>>(
        ah, al, wh, wl, up, nullptr, nullptr, SQ, IDIM, HD);
    {
        int n = SQ * IDIM;
        silu_mul_kernel<<<(n + 255) / 256, 256>>>(gate, up, gate, n);
    }
    do_split(gate, ah, al, SQ * IDIM);
    do_split(down_w, wh, wl, HD * IDIM);
    gemm_mma<<<dim3(HD / 128, SQ / 128), 512, gsmem>>>(
        ah, al, wh, wl, out, nullptr, x2, SQ, HD, IDIM);
}

// round 15
// speedup vs baseline: 1.6711x; 1.0162x over previous
#include <cuda_runtime.h>
#include <cuda_bf16.h>
#include <math.h>
#include <stdint.h>

#define SQ 2048
#define HD 4096
#define NH 32
#define NKV 8
#define DH 128
#define IDIM 11008
#define EPSR 1e-6f
#define NEGF -3.0e38f

// ---------------- fp32 scratch ----------------
__device__ float g_cat [SQ * 2 * HD];
__device__ float g_x   [SQ * HD];
__device__ float g_h   [SQ * HD];
__device__ float g_q   [SQ * NH * DH];
__device__ float g_k   [SQ * NKV * DH];
__device__ float g_v   [SQ * NKV * DH];
__device__ float g_attn[SQ * NH * DH];
__device__ float g_x2  [SQ * HD];
__device__ float g_gate[SQ * IDIM];
__device__ float g_up  [SQ * IDIM];

// ---------------- shared bf16 hi/lo scratch (split on demand) ----------------
#define WSCR (IDIM * HD)
#define ASCR (SQ * IDIM)
__device__ __nv_bfloat16 g_wh[WSCR], g_wl[WSCR];
__device__ __nv_bfloat16 g_ah[ASCR], g_al[ASCR];

// ---------------- PTX helpers ----------------
__device__ __forceinline__ uint32_t s2u(const void* p) {
    uint32_t a;
    asm("{ .reg .u64 t; cvta.to.shared.u64 t, %1; cvt.u32.u64 %0, t; }" : "=r"(a) : "l"(p));
    return a;
}
__device__ __forceinline__ void cp16(uint32_t s, const void* g) {
    asm volatile("cp.async.cg.shared.global [%0], [%1], 16;" :: "r"(s), "l"(g));
}
#define CP_COMMIT() asm volatile("cp.async.commit_group;")

__device__ __forceinline__ void ldsm4(uint32_t a[4], uint32_t addr) {
    asm volatile("ldmatrix.sync.aligned.m8n8.x4.shared.b16 {%0,%1,%2,%3}, [%4];"
                 : "=r"(a[0]), "=r"(a[1]), "=r"(a[2]), "=r"(a[3]) : "r"(addr));
}
__device__ __forceinline__ void mma16816(float c[4], const uint32_t a[4], const uint32_t b[2]) {
    asm volatile(
        "mma.sync.aligned.m16n8k16.row.col.f32.bf16.bf16.f32 "
        "{%0,%1,%2,%3}, {%4,%5,%6,%7}, {%8,%9}, {%0,%1,%2,%3};"
        : "+f"(c[0]), "+f"(c[1]), "+f"(c[2]), "+f"(c[3])
        : "r"(a[0]), "r"(a[1]), "r"(a[2]), "r"(a[3]), "r"(b[0]), "r"(b[1]));
}

// ---------------- fp32 -> bf16 hi/lo split ----------------
__global__ void split_bf16(const float* __restrict__ x,
                           __nv_bfloat16* __restrict__ h,
                           __nv_bfloat16* __restrict__ l, int n) {
    int i = (blockIdx.x * blockDim.x + threadIdx.x) * 4;
    if (i >= n) return;
    float4 v = *(const float4*)(x + i);
    __nv_bfloat16 h0 = __float2bfloat16(v.x);
    __nv_bfloat16 h1 = __float2bfloat16(v.y);
    __nv_bfloat16 h2 = __float2bfloat16(v.z);
    __nv_bfloat16 h3 = __float2bfloat16(v.w);
    __nv_bfloat16 l0 = __float2bfloat16(v.x - __bfloat162float(h0));
    __nv_bfloat16 l1 = __float2bfloat16(v.y - __bfloat162float(h1));
    __nv_bfloat16 l2 = __float2bfloat16(v.z - __bfloat162float(h2));
    __nv_bfloat16 l3 = __float2bfloat16(v.w - __bfloat162float(h3));
    __nv_bfloat162 a; a.x = h0; a.y = h1;
    __nv_bfloat162 b; b.x = h2; b.y = h3;
    __nv_bfloat162 c; c.x = l0; c.y = l1;
    __nv_bfloat162 d; d.x = l2; d.y = l3;
    *(__nv_bfloat162*)(h + i)     = a;
    *(__nv_bfloat162*)(h + i + 2) = b;
    *(__nv_bfloat162*)(l + i)     = c;
    *(__nv_bfloat162*)(l + i + 2) = d;
}

// ---------------- HMMA GEMM: C[M,N] = A[M,K]*B[N,K]^T (+bias)(+res), 3-term bf16 ----------------
// CTA 256x128, BK=64, 2-stage cp.async. 16 warps = 8(M) x 2(N), warp tile 32x64.
#define LDSW 72                        // smem row stride in bf16 (144B: 16B-aligned, ldmatrix-legal)
#define ATILE (256 * LDSW * 2)         // 36864 B per A matrix tile
#define BTILE (128 * LDSW * 2)         // 18432 B per B matrix tile
#define STAGE2 (2u * ATILE + 2u * BTILE)  // 110592 B per stage

__global__ void __launch_bounds__(512, 1)
gemm_mma(const __nv_bfloat16* __restrict__ Ah, const __nv_bfloat16* __restrict__ Al,
         const __nv_bfloat16* __restrict__ Bh, const __nv_bfloat16* __restrict__ Bl,
         float* __restrict__ C, const float* __restrict__ bias, const float* __restrict__ res,
         int M, int N, int K) {
    extern __shared__ char smem[];
    uint32_t sb = s2u(smem);
    int tid = threadIdx.x;
    int wid = tid >> 5, lane = tid & 31;
    int wm = wid >> 1, wn = wid & 1;          // 8x2 warp grid, warp tile 32x64
    int bm = blockIdx.y * 256;
    int bn = blockIdx.x * 128;

    float acc[2][8][4];
#pragma unroll
    for (int i = 0; i < 2; i++)
#pragma unroll
        for (int j = 0; j < 8; j++)
#pragma unroll
            for (int t = 0; t < 4; t++) acc[i][j][t] = 0.f;

#define LOADC(c) do { \
        uint32_t st = sb + (uint32_t)((c) & 1) * STAGE2; \
        int k0 = (c) << 6; \
        _Pragma("unroll") \
        for (int it = 0; it < 4; it++) { \
            int idx = tid + it * 512; \
            int row = idx >> 3, col = (idx & 7) * 8; \
            uint32_t so = (uint32_t)(row * LDSW + col) * 2; \
            size_t ga = (size_t)(bm + row) * K + k0 + col; \
            cp16(st + so,         Ah + ga); \
            cp16(st + ATILE + so, Al + ga); \
        } \
        _Pragma("unroll") \
        for (int it = 0; it < 2; it++) { \
            int idx = tid + it * 512; \
            int row = idx >> 3, col = (idx & 7) * 8; \
            uint32_t so = (uint32_t)(row * LDSW + col) * 2; \
            size_t gb = (size_t)(bn + row) * K + k0 + col; \
            cp16(st + 2 * ATILE + so,         Bh + gb); \
            cp16(st + 2 * ATILE + BTILE + so, Bl + gb); \
        } \
        CP_COMMIT(); \
    } while (0)

    int nc = K >> 6;
    LOADC(0);

    for (int c = 0; c < nc; c++) {
        if (c + 1 < nc) {
            LOADC(c + 1);
            asm volatile("cp.async.wait_group 1;");
        } else {
            asm volatile("cp.async.wait_group 0;");
        }
        __syncthreads();

        uint32_t sA  = sb + (uint32_t)(c & 1) * STAGE2;
        uint32_t sBh = sA + 2 * ATILE;
        int arow = wm * 32 + (lane & 15);
        int brow = wn * 64 + (lane & 15);
        int koff = ((lane >> 4) & 1) * 8;

#pragma unroll
        for (int k16 = 0; k16 < 64; k16 += 16) {
            uint32_t ah[2][4], al[2][4];
#pragma unroll
            for (int i = 0; i < 2; i++) {
                uint32_t ad = sA + (uint32_t)((arow + i * 16) * LDSW + k16 + koff) * 2;
                ldsm4(ah[i], ad);
                ldsm4(al[i], ad + ATILE);
            }
#pragma unroll
            for (int j2 = 0; j2 < 4; j2++) {
                uint32_t bd = sBh + (uint32_t)((brow + j2 * 16) * LDSW + k16 + koff) * 2;
                uint32_t t[4];
                uint32_t bhf[2][2], blf[2][2];
                // ldmatrix.x4: t0=(n0-7,k0-7) t1=(n8-15,k0-7) t2=(n0-7,k8-15) t3=(n8-15,k8-15)
                ldsm4(t, bd);
                bhf[0][0] = t[0]; bhf[0][1] = t[2];
                bhf[1][0] = t[1]; bhf[1][1] = t[3];
                ldsm4(t, bd + BTILE);
                blf[0][0] = t[0]; blf[0][1] = t[2];
                blf[1][0] = t[1]; blf[1][1] = t[3];
#pragma unroll
                for (int i = 0; i < 2; i++)
#pragma unroll
                    for (int jj = 0; jj < 2; jj++) {
                        int j = j2 * 2 + jj;
                        mma16816(acc[i][j], ah[i], bhf[jj]);
                        mma16816(acc[i][j], ah[i], blf[jj]);
                        mma16816(acc[i][j], al[i], bhf[jj]);
                    }
            }
        }
        __syncthreads();
    }

    // epilogue
    int tr = lane >> 2, tc = (lane & 3) * 2;
    int r0 = bm + wm * 32;
    int c0 = bn + wn * 64;
#pragma unroll
    for (int i = 0; i < 2; i++) {
#pragma unroll
        for (int j = 0; j < 8; j++) {
            int grow = r0 + i * 16 + tr;
            int gcol = c0 + j * 8 + tc;
            float2 v0, v1;
            v0.x = acc[i][j][0]; v0.y = acc[i][j][1];
            v1.x = acc[i][j][2]; v1.y = acc[i][j][3];
            if (bias) {
                float b0 = bias[gcol], b1 = bias[gcol + 1];
                v0.x += b0; v0.y += b1;
                v1.x += b0; v1.y += b1;
            }
            size_t i0 = (size_t)grow * N + gcol;
            size_t i1 = (size_t)(grow + 8) * N + gcol;
            if (res) {
                float2 r0v = *(const float2*)(res + i0);
                float2 r1v = *(const float2*)(res + i1);
                v0.x += r0v.x; v0.y += r0v.y;
                v1.x += r1v.x; v1.y += r1v.y;
            }
            *(float2*)(C + i0) = v0;
            *(float2*)(C + i1) = v1;
        }
    }
}

// ---------------- concat ----------------
__global__ void concat_kernel(const float* __restrict__ embeds,
                              const float* __restrict__ hidden,
                              float* __restrict__ out) {
    int t = blockIdx.x * blockDim.x + threadIdx.x;
    int e = t * 4;
    if (e >= SQ * 2 * HD) return;
    int s = e >> 13;
    int i = e & 8191;
    const float* src = (i < HD) ? (embeds + s * HD + i) : (hidden + s * HD + (i - HD));
    *(float4*)(out + e) = *(const float4*)src;
}

// ---------------- rmsnorm ----------------
__global__ void rmsnorm_kernel(const float* __restrict__ x,
                               const float* __restrict__ w,
                               float* __restrict__ out) {
    int row = blockIdx.x;
    const float* xr = x + (size_t)row * HD;
    float ss = 0.f;
    for (int i = threadIdx.x; i < HD; i += 256) { float v = xr[i]; ss += v * v; }
    __shared__ float red[256];
    red[threadIdx.x] = ss;
    __syncthreads();
    for (int o = 128; o > 0; o >>= 1) {
        if (threadIdx.x < o) red[threadIdx.x] += red[threadIdx.x + o];
        __syncthreads();
    }
    float scale = rsqrtf(red[0] / (float)HD + EPSR);
    for (int i = threadIdx.x; i < HD; i += 256)
        out[(size_t)row * HD + i] = xr[i] * scale * w[i];
}

// ---------------- rope ----------------
__global__ void rope_kernel(float* __restrict__ q, float* __restrict__ k) {
    int b = blockIdx.x;
    int s = b / (NH + NKV);
    int h = b - s * (NH + NKV);
    float* ptr = (h < NH) ? (q + ((size_t)s * NH + h) * DH)
                          : (k + ((size_t)s * NKV + (h - NH)) * DH);
    int d = threadIdx.x;
    __shared__ float row[DH];
    row[d] = ptr[d];
    __syncthreads();
    int j = d & 63;
    double invf = pow(10000.0, -(double)j / 64.0);
    float ang = (float)((double)s * invf);
    float c  = (float)cos((double)ang);
    float sn = (float)sin((double)ang);
    float rot = (d < 64) ? -row[d + 64] : row[d - 64];
    ptr[d] = row[d] * c + rot * sn;
}

// ---------------- silu(gate) * up ----------------
__global__ void silu_mul_kernel(const float* __restrict__ g,
                                const float* __restrict__ u,
                                float* __restrict__ out, int n) {
    int i = blockIdx.x * blockDim.x + threadIdx.x;
    if (i < n) {
        float x = g[i];
        float s = x / (1.f + expf(-x));
        out[i] = s * u[i];
    }
}

// ---------------- flash attention (fp32, causal, GQA) ----------------
#define BQT 64
#define BKT 64
__global__ void __launch_bounds__(256, 1)
attn_kernel(const float* __restrict__ q, const float* __restrict__ k,
            const float* __restrict__ v, const float* __restrict__ amask,
            float* __restrict__ out) {
    extern __shared__ float sm[];
    float* Qs = sm;
    float* Ks = Qs + BQT * DH;
    float* Vs = Ks + BKT * DH;
    float* Ps = Vs + BKT * DH;

    int qt = blockIdx.x;
    int h  = blockIdx.y;
    int kvh = h >> 2;
    int tid = threadIdx.x;
    int r  = tid >> 2;
    int cq = tid & 3;

    const float* qbase = q + (size_t)(qt * BQT) * NH * DH + h * DH;
    for (int i = tid; i < BQT * DH / 4; i += 256) {
        int rr = i >> 5;
        int dd = (i & 31) * 4;
        *(float4*)&Qs[rr * DH + dd] = *(const float4*)&qbase[(size_t)rr * NH * DH + dd];
    }

    float m = NEGF, l = 0.f;
    float acc[32];
#pragma unroll
    for (int j = 0; j < 32; j++) acc[j] = 0.f;

    const float scale = 0.08838834764831845f;

    for (int kt = 0; kt <= qt; kt++) {
        __syncthreads();
        const float* kbase = k + (size_t)(kt * BKT) * NKV * DH + kvh * DH;
        const float* vbase = v + (size_t)(kt * BKT) * NKV * DH + kvh * DH;
        for (int i = tid; i < BKT * DH / 4; i += 256) {
            int rr = i >> 5;
            int dd = (i & 31) * 4;
            *(float4*)&Ks[rr * DH + dd] = *(const float4*)&kbase[(size_t)rr * NKV * DH + dd];
            *(float4*)&Vs[rr * DH + dd] = *(const float4*)&vbase[(size_t)rr * NKV * DH + dd];
        }
        __syncthreads();

        float s[16];
#pragma unroll
        for (int cc = 0; cc < 16; cc++) s[cc] = 0.f;
        const float* qrow = &Qs[r * DH];
#pragma unroll 4
        for (int d0 = 0; d0 < DH; d0 += 16) {
            float4 q0 = *(const float4*)&qrow[d0];
            float4 q1 = *(const float4*)&qrow[d0 + 4];
            float4 q2 = *(const float4*)&qrow[d0 + 8];
            float4 q3 = *(const float4*)&qrow[d0 + 12];
#pragma unroll
            for (int cc = 0; cc < 16; cc++) {
                const float* krow = &Ks[(cc * 4 + cq) * DH + d0];
                float4 k0 = *(const float4*)&krow[0];
                float4 k1 = *(const float4*)&krow[4];
                float4 k2 = *(const float4*)&krow[8];
                float4 k3 = *(const float4*)&krow[12];
                s[cc] += q0.x * k0.x + q0.y * k0.y + q0.z * k0.z + q0.w * k0.w
                       + q1.x * k1.x + q1.y * k1.y + q1.z * k1.z + q1.w * k1.w
                       + q2.x * k2.x + q2.y * k2.y + q2.z * k2.z + q2.w * k2.w
                       + q3.x * k3.x + q3.y * k3.y + q3.z * k3.z + q3.w * k3.w;
            }
        }

        int qi = qt * BQT + r;
        float tmax = NEGF;
#pragma unroll
        for (int cc = 0; cc < 16; cc++) {
            int kj = kt * BKT + cc * 4 + cq;
            float sc = s[cc] * scale;
            if (kj > qi) sc = NEGF;
            else if (amask[kj] <= 0.5f) sc = NEGF;
            s[cc] = sc;
            tmax = fmaxf(tmax, sc);
        }
        tmax = fmaxf(tmax, __shfl_xor_sync(0xffffffffu, tmax, 1));
        tmax = fmaxf(tmax, __shfl_xor_sync(0xffffffffu, tmax, 2));
        float mnew = fmaxf(m, tmax);
        float corr = expf(m - mnew);
        float psum = 0.f;
#pragma unroll
        for (int cc = 0; cc < 16; cc++) {
            float p = expf(s[cc] - mnew);
            Ps[r * 64 + cc * 4 + cq] = p;
            psum += p;
        }
        psum += __shfl_xor_sync(0xffffffffu, psum, 1);
        psum += __shfl_xor_sync(0xffffffffu, psum, 2);
        l = l * corr + psum;
        m = mnew;
#pragma unroll
        for (int j = 0; j < 32; j++) acc[j] *= corr;
        __syncthreads();

        const float* vb = &Vs[cq * 32];
#pragma unroll 8
        for (int c = 0; c < 64; c++) {
            float pv = Ps[r * 64 + c];
            const float* vrow = vb + c * DH;
#pragma unroll
            for (int j = 0; j < 8; j++) {
                float4 vv = *(const float4*)&vrow[j * 4];
                acc[j * 4 + 0] += pv * vv.x;
                acc[j * 4 + 1] += pv * vv.y;
                acc[j * 4 + 2] += pv * vv.z;
                acc[j * 4 + 3] += pv * vv.w;
            }
        }
    }

    float invl = 1.f / l;
    float* ob = out + (size_t)(qt * BQT + r) * (NH * DH) + h * DH + cq * 32;
#pragma unroll
    for (int j = 0; j < 8; j++) {
        float4 o;
        o.x = acc[j * 4 + 0] * invl;
        o.y = acc[j * 4 + 1] * invl;
        o.z = acc[j * 4 + 2] * invl;
        o.w = acc[j * 4 + 3] * invl;
        *(float4*)&ob[j * 4] = o;
    }
}

// ---------------- launch ----------------
static void do_split(const float* src, __nv_bfloat16* h, __nv_bfloat16* l, int n) {
    split_bf16<<<(n / 4 + 255) / 256, 256>>>(src, h, l, n);
}

extern "C" void kernel_launch(void* const* d_in, const int* in_sizes, int n_in,
                              void* d_out, int out_size) {
    const float* hidden  = (const float*)d_in[0];
    const float* embeds  = (const float*)d_in[1];
    const float* amask   = (const float*)d_in[2];
    const float* fc_w    = (const float*)d_in[3];
    const float* fc_b    = (const float*)d_in[4];
    const float* in_norm = (const float*)d_in[5];
    const float* q_w     = (const float*)d_in[6];
    const float* k_w     = (const float*)d_in[7];
    const float* v_w     = (const float*)d_in[8];
    const float* o_w     = (const float*)d_in[9];
    const float* post_nw = (const float*)d_in[10];
    const float* gate_w  = (const float*)d_in[11];
    const float* up_w    = (const float*)d_in[12];
    const float* down_w  = (const float*)d_in[13];
    float* out = (float*)d_out;

    float *cat, *x, *hbuf, *qb, *kb, *vb, *attn, *x2, *gate, *up;
    cudaGetSymbolAddress((void**)&cat,  g_cat);
    cudaGetSymbolAddress((void**)&x,    g_x);
    cudaGetSymbolAddress((void**)&hbuf, g_h);
    cudaGetSymbolAddress((void**)&qb,   g_q);
    cudaGetSymbolAddress((void**)&kb,   g_k);
    cudaGetSymbolAddress((void**)&vb,   g_v);
    cudaGetSymbolAddress((void**)&attn, g_attn);
    cudaGetSymbolAddress((void**)&x2,   g_x2);
    cudaGetSymbolAddress((void**)&gate, g_gate);
    cudaGetSymbolAddress((void**)&up,   g_up);

    __nv_bfloat16 *wh, *wl, *ah, *al;
    cudaGetSymbolAddress((void**)&wh, g_wh);
    cudaGetSymbolAddress((void**)&wl, g_wl);
    cudaGetSymbolAddress((void**)&ah, g_ah);
    cudaGetSymbolAddress((void**)&al, g_al);

    int gsmem = 2 * (int)STAGE2;   // 221184
    cudaFuncSetAttribute(gemm_mma, cudaFuncAttributeMaxDynamicSharedMemorySize, gsmem);
    int asmem = (3 * BQT * DH + BQT * BKT) * (int)sizeof(float);
    cudaFuncSetAttribute(attn_kernel, cudaFuncAttributeMaxDynamicSharedMemorySize, asmem);

    // concat + split A
    {
        int n4 = SQ * 2 * HD / 4;
        concat_kernel<<<(n4 + 255) / 256, 256>>>(embeds, hidden, cat);
    }
    do_split(cat, ah, al, SQ * 2 * HD);
    do_split(fc_w, wh, wl, HD * 2 * HD);
    gemm_mma<<<dim3(HD / 128, SQ / 256), 512, gsmem>>>(
        ah, al, wh, wl, x, fc_b, nullptr, SQ, HD, 2 * HD);

    // in-norm + split
    rmsnorm_kernel<<<SQ, 256>>>(x, in_norm, hbuf);
    do_split(hbuf, ah, al, SQ * HD);

    // q/k/v
    do_split(q_w, wh, wl, HD * HD);
    gemm_mma<<<dim3(NH * DH / 128, SQ / 256), 512, gsmem>>>(
        ah, al, wh, wl, qb, nullptr, nullptr, SQ, NH * DH, HD);
    do_split(k_w, wh, wl, NKV * DH * HD);
    gemm_mma<<<dim3(NKV * DH / 128, SQ / 256), 512, gsmem>>>(
        ah, al, wh, wl, kb, nullptr, nullptr, SQ, NKV * DH, HD);
    do_split(v_w, wh, wl, NKV * DH * HD);
    gemm_mma<<<dim3(NKV * DH / 128, SQ / 256), 512, gsmem>>>(
        ah, al, wh, wl, vb, nullptr, nullptr, SQ, NKV * DH, HD);

    // rope
    rope_kernel<<<SQ * (NH + NKV), DH>>>(qb, kb);

    // attention
    attn_kernel<<<dim3(SQ / BQT, NH), 256, asmem>>>(qb, kb, vb, amask, attn);

    // o-proj + residual
    do_split(attn, ah, al, SQ * HD);
    do_split(o_w, wh, wl, HD * HD);
    gemm_mma<<<dim3(HD / 128, SQ / 256), 512, gsmem>>>(
        ah, al, wh, wl, x2, nullptr, x, SQ, HD, NH * DH);

    // post-norm + split
    rmsnorm_kernel<<<SQ, 256>>>(x2, post_nw, hbuf);
    do_split(hbuf, ah, al, SQ * HD);

    // mlp
    do_split(gate_w, wh, wl, IDIM * HD);
    gemm_mma<<<dim3(IDIM / 128, SQ / 256), 512, gsmem>>>(
        ah, al, wh, wl, gate, nullptr, nullptr, SQ, IDIM, HD);
    do_split(up_w, wh, wl, IDIM * HD);
    gemm_mma<<<dim3(IDIM / 128, SQ / 256), 512, gsmem>>>(
        ah, al, wh, wl, up, nullptr, nullptr, SQ, IDIM, HD);
    {
        int n = SQ * IDIM;
        silu_mul_kernel<<<(n + 255) / 256, 256>>>(gate, up, gate, n);
    }
    do_split(gate, ah, al, SQ * IDIM);
    do_split(down_w, wh, wl, HD * IDIM);
    gemm_mma<<<dim3(HD / 128, SQ / 256), 512, gsmem>>>(
        ah, al, wh, wl, out, nullptr, x2, SQ, HD, IDIM);
}